// round 2
// baseline (speedup 1.0000x reference)
#include <cuda_runtime.h>
#include <math.h>

// Problem constants (fixed by setup_inputs)
#define B_ROWS   8192
#define NBINS    125
#define M_CAND   4096

constexpr float D2R     = 0.017453292519943295f; // pi/180
constexpr float TAU     = 0.25f;
constexpr float K_SCALE = 2.0f * 3958.8f / 0.25f; // 2*R/tau
#define NEG_BIG (-1.0e30f)

// Scratch (static device arrays are allowed)
__device__ float4 g_pre[NBINS * M_CAND];   // (half_lat_rad, half_lon_rad, cos_lat, pad)
__device__ float  g_softmin[B_ROWS];
__device__ float  g_validf[B_ROWS];
__device__ int    g_is64;                  // 1 if integer inputs are int64, 0 if int32

// ---------------------------------------------------------------------------
// Kernel 0: detect integer width of x_vals (values must all be in [0,5))
// Reads only first 64 rows as int64 = 1536 bytes, in-bounds for either dtype.
// ---------------------------------------------------------------------------
__global__ void detect_kernel(const void* __restrict__ x_vals_raw) {
    if (threadIdx.x == 0 && blockIdx.x == 0) {
        const long long* p64 = (const long long*)x_vals_raw;
        int ok = 1;
        #pragma unroll 1
        for (int i = 0; i < 64 * 3; i++) {
            long long v = p64[i];
            if (v < 0 || v > 4) { ok = 0; break; }
        }
        g_is64 = ok;
    }
}

// ---------------------------------------------------------------------------
// Kernel 1: precompute per-candidate trig terms (125*4096 = 512K elements)
// ---------------------------------------------------------------------------
__global__ void precompute_kernel(const float* __restrict__ bin_coords) {
    int i = blockIdx.x * blockDim.x + threadIdx.x;
    if (i < NBINS * M_CAND) {
        float lon = bin_coords[2 * i + 0];
        float lat = bin_coords[2 * i + 1];
        float latr = lat * D2R;
        float lonr = lon * D2R;
        g_pre[i] = make_float4(0.5f * latr, 0.5f * lonr, cosf(latr), 0.0f);
    }
}

// ---------------------------------------------------------------------------
// Kernel 2: one warp per row — streaming haversine + online logsumexp
// ---------------------------------------------------------------------------
__global__ void __launch_bounds__(256) row_kernel(
    const float* __restrict__ preds,        // [B,2] (lon, lat)
    const void*  __restrict__ x_vals_raw,   // [B,3] int32 or int64
    const void*  __restrict__ bin_counts_raw) // [NBINS] int32 or int64
{
    int warp_in_blk = threadIdx.x >> 5;
    int lane        = threadIdx.x & 31;
    int row = blockIdx.x * (blockDim.x >> 5) + warp_in_blk;
    if (row >= B_ROWS) return;

    const int is64 = g_is64;

    int bin, count;
    if (is64) {
        const long long* xv = (const long long*)x_vals_raw;
        const long long* bc = (const long long*)bin_counts_raw;
        bin   = (int)(xv[3 * row + 0] * 25 + xv[3 * row + 1] * 5 + xv[3 * row + 2]);
        count = (int)bc[bin];
    } else {
        const int* xv = (const int*)x_vals_raw;
        const int* bc = (const int*)bin_counts_raw;
        bin   = xv[3 * row + 0] * 25 + xv[3 * row + 1] * 5 + xv[3 * row + 2];
        count = bc[bin];
    }

    float lon1 = preds[2 * row + 0];
    float lat1 = preds[2 * row + 1];
    float lat1r = lat1 * D2R;
    float h1lat = 0.5f * lat1r;
    float h1lon = 0.5f * (lon1 * D2R);
    float c1    = cosf(lat1r);

    const float4* __restrict__ pre = g_pre + (size_t)bin * M_CAND;

    // online logsumexp state over logits = -K_SCALE * asin(sqrt(a))
    float m = NEG_BIG;
    float s = 0.0f;

    #pragma unroll 4
    for (int i = lane; i < count; i += 32) {
        float4 p = pre[i];                 // hlat2, hlon2, clat2
        float sdlat = __sinf(p.x - h1lat);
        float sdlon = __sinf(p.y - h1lon);
        float a = fmaf(sdlat, sdlat, (c1 * p.z) * (sdlon * sdlon));
        a = fminf(a, 1.0f);
        float c = asinf(sqrtf(a));
        float logit = -K_SCALE * c;

        // single-exp online update
        float d = logit - m;
        float e = __expf(-fabsf(d));       // exp(-|d|); exp(-big)=0, safe
        if (d > 0.0f) { s = fmaf(s, e, 1.0f); m = logit; }
        else          { s += e; }
    }

    // warp-level (m, s) merge
    #pragma unroll
    for (int off = 16; off > 0; off >>= 1) {
        float mo = __shfl_xor_sync(0xFFFFFFFFu, m, off);
        float so = __shfl_xor_sync(0xFFFFFFFFu, s, off);
        float mn = fmaxf(m, mo);
        // NEG_BIG sentinel keeps (m - mn) finite: no NaN from empty lanes
        s = s * __expf(m - mn) + so * __expf(mo - mn);
        m = mn;
    }

    if (lane == 0) {
        bool valid = (count > 0);
        g_softmin[row] = valid ? (-TAU * (m + __logf(s))) : 0.0f;
        g_validf[row]  = valid ? 1.0f : 0.0f;
    }
}

// ---------------------------------------------------------------------------
// Kernel 3: deterministic final reduction over B rows
// ---------------------------------------------------------------------------
__global__ void __launch_bounds__(256) reduce_kernel(float* __restrict__ out) {
    __shared__ float sm_s[256];
    __shared__ float sm_v[256];
    int tid = threadIdx.x;
    float s = 0.0f, v = 0.0f;
    for (int i = tid; i < B_ROWS; i += 256) {
        s += g_softmin[i];
        v += g_validf[i];
    }
    sm_s[tid] = s; sm_v[tid] = v;
    __syncthreads();
    for (int off = 128; off > 0; off >>= 1) {
        if (tid < off) {
            sm_s[tid] += sm_s[tid + off];
            sm_v[tid] += sm_v[tid + off];
        }
        __syncthreads();
    }
    if (tid == 0) {
        out[0] = sm_s[0] / fmaxf(sm_v[0], 1.0f);
    }
}

// ---------------------------------------------------------------------------
// Launch — inputs identified by element count (immune to ordering):
//   preds_lonlat : 8192*2      = 16384
//   bin_coords   : 125*4096*2  = 1024000
//   x_vals       : 8192*3      = 24576  (or 49152 if counted as int32 halves)
//   bin_counts   : 125         (or 250)
// ---------------------------------------------------------------------------
extern "C" void kernel_launch(void* const* d_in, const int* in_sizes, int n_in,
                              void* d_out, int out_size) {
    const float* preds      = nullptr;
    const float* bin_coords = nullptr;
    const void*  x_vals     = nullptr;
    const void*  bin_counts = nullptr;

    for (int i = 0; i < n_in; i++) {
        switch (in_sizes[i]) {
            case 16384:   preds      = (const float*)d_in[i]; break;
            case 1024000: bin_coords = (const float*)d_in[i]; break;
            case 24576:
            case 49152:   x_vals     = d_in[i]; break;
            case 125:
            case 250:     bin_counts = d_in[i]; break;
            default: break;
        }
    }

    detect_kernel<<<1, 32>>>(x_vals);

    const int NPRE = NBINS * M_CAND;
    precompute_kernel<<<(NPRE + 255) / 256, 256>>>(bin_coords);

    // one warp per row: 8192 warps, 8 warps (256 thr) per block
    row_kernel<<<B_ROWS / 8, 256>>>(preds, x_vals, bin_counts);

    reduce_kernel<<<1, 256>>>(d_out ? (float*)d_out : nullptr);
}

// round 3
// speedup vs baseline: 1.4270x; 1.4270x over previous
#include <cuda_runtime.h>
#include <math.h>

// Problem constants (fixed by setup_inputs)
#define B_ROWS   8192
#define NBINS    125
#define M_CAND   4096
#define ROWCAP   512          // max rows per bin (mean 65.5, sigma 8.1 -> 55 sigma)
#define TILE     1024         // candidates per smem tile (16 KB)

constexpr float D2R      = 0.017453292519943295f; // pi/180
constexpr float TAU      = 0.25f;
constexpr float INV_TAU  = 4.0f;
constexpr float TWO_R    = 2.0f * 3958.8f;
// chord-space slack: dist cutoff 4.03 miles (exp(-16.1)=1e-7) -> dchord <= dd/R = 1.02e-3
constexpr float CHORD_SLACK = 1.3e-3f;

// Scratch (static device arrays)
__device__ float4 g_vec[NBINS * M_CAND];   // candidate unit vectors (x,y,z,_)
__device__ float4 g_pred[B_ROWS];          // pred unit vectors
__device__ int    g_bin_rows[NBINS * ROWCAP];
__device__ int    g_bin_nrows[NBINS];
__device__ float  g_softmin[B_ROWS];
__device__ float  g_validf[B_ROWS];
__device__ int    g_is64;

// ---------------------------------------------------------------------------
// Kernel 0: parallel int-width detect + zero bin counters
// Reads first 64 rows of x_vals as int64 (1536 B, in-bounds either dtype);
// all values in [0,5) only if truly int64.
// ---------------------------------------------------------------------------
__global__ void detect_kernel(const void* __restrict__ x_vals_raw) {
    __shared__ int bad;
    if (threadIdx.x == 0) bad = 0;
    __syncthreads();
    if (threadIdx.x < 192) {
        long long v = ((const long long*)x_vals_raw)[threadIdx.x];
        if (v < 0 || v > 4) bad = 1;   // benign race
    }
    if (threadIdx.x < NBINS) g_bin_nrows[threadIdx.x] = 0;
    __syncthreads();
    if (threadIdx.x == 0) g_is64 = !bad;
}

// ---------------------------------------------------------------------------
// Kernel 1: candidate unit vectors (512K elements, one-time trig)
// ---------------------------------------------------------------------------
__global__ void precompute_kernel(const float* __restrict__ bin_coords) {
    int i = blockIdx.x * blockDim.x + threadIdx.x;
    if (i < NBINS * M_CAND) {
        float2 c = ((const float2*)bin_coords)[i];   // (lon, lat)
        float lonr = c.x * D2R;
        float latr = c.y * D2R;
        float sla, cla, slo, clo;
        sincosf(latr, &sla, &cla);
        sincosf(lonr, &slo, &clo);
        g_vec[i] = make_float4(cla * clo, cla * slo, sla, 0.0f);
    }
}

// ---------------------------------------------------------------------------
// Kernel 2: bucket rows by bin + pred unit vectors
// (atomic slot order only affects warp->row mapping, not any fp sum order:
//  results land in g_softmin[row]; final reduce is fixed-order -> deterministic)
// ---------------------------------------------------------------------------
__global__ void binning_kernel(const float* __restrict__ preds,
                               const void*  __restrict__ x_vals_raw) {
    int r = blockIdx.x * blockDim.x + threadIdx.x;
    if (r >= B_ROWS) return;

    int bin;
    if (g_is64) {
        const long long* xv = (const long long*)x_vals_raw;
        bin = (int)(xv[3 * r + 0] * 25 + xv[3 * r + 1] * 5 + xv[3 * r + 2]);
    } else {
        const int* xv = (const int*)x_vals_raw;
        bin = xv[3 * r + 0] * 25 + xv[3 * r + 1] * 5 + xv[3 * r + 2];
    }
    int slot = atomicAdd(&g_bin_nrows[bin], 1);
    if (slot < ROWCAP) g_bin_rows[bin * ROWCAP + slot] = r;

    float lonr = preds[2 * r + 0] * D2R;
    float latr = preds[2 * r + 1] * D2R;
    float sla, cla, slo, clo;
    sincosf(latr, &sla, &cla);
    sincosf(lonr, &slo, &clo);
    g_pred[r] = make_float4(cla * clo, cla * slo, sla, 0.0f);
}

// ---------------------------------------------------------------------------
// Kernel 3: main — one block per (bin, 8-row chunk), smem-tiled candidates.
// Phase A: hard min of squared-chord q = |u-v|^2 (pure FMA, no trig).
// Phase B: exact asin/exp only for q within the soft-min tail window.
// ---------------------------------------------------------------------------
__global__ void __launch_bounds__(256) main_kernel(const void* __restrict__ bin_counts_raw) {
    __shared__ float4 tile[TILE];

    int bin   = blockIdx.x;
    int nrows = min(g_bin_nrows[bin], ROWCAP);
    int rbase = blockIdx.y * 8;
    if (rbase >= nrows) return;

    int count;
    if (g_is64) count = (int)((const long long*)bin_counts_raw)[bin];
    else        count = ((const int*)bin_counts_raw)[bin];
    count = min(count, M_CAND);

    int warp = threadIdx.x >> 5;
    int lane = threadIdx.x & 31;
    int has  = (rbase + warp) < nrows;
    int row  = has ? g_bin_rows[bin * ROWCAP + rbase + warp] : 0;

    float4 u = g_pred[row];
    const float4* __restrict__ pre = g_vec + (size_t)bin * M_CAND;

    // ---- Phase A: min squared chord ----
    float q0 = 3.0e38f, q1 = 3.0e38f;
    for (int t0 = 0; t0 < count; t0 += TILE) {
        int tn = min(TILE, count - t0);
        __syncthreads();
        for (int j = threadIdx.x; j < tn; j += 256) tile[j] = pre[t0 + j];
        __syncthreads();
        if (has) {
            int i = lane;
            for (; i + 32 < tn; i += 64) {
                float4 v = tile[i];
                float dx = v.x - u.x, dy = v.y - u.y, dz = v.z - u.z;
                q0 = fminf(q0, fmaf(dx, dx, fmaf(dy, dy, dz * dz)));
                float4 w = tile[i + 32];
                float ex = w.x - u.x, ey = w.y - u.y, ez = w.z - u.z;
                q1 = fminf(q1, fmaf(ex, ex, fmaf(ey, ey, ez * ez)));
            }
            if (i < tn) {
                float4 v = tile[i];
                float dx = v.x - u.x, dy = v.y - u.y, dz = v.z - u.z;
                q0 = fminf(q0, fmaf(dx, dx, fmaf(dy, dy, dz * dz)));
            }
        }
    }
    float qm = fminf(q0, q1);
    #pragma unroll
    for (int off = 16; off > 0; off >>= 1)
        qm = fminf(qm, __shfl_xor_sync(0xFFFFFFFFu, qm, off));

    float chord = sqrtf(qm);
    float dmin  = TWO_R * asinf(0.5f * chord);   // exact min distance (miles)
    float tc    = chord + CHORD_SLACK;
    float qthr  = tc * tc;

    // ---- Phase B: exact soft-min tail near the minimum ----
    float s = 0.0f;
    for (int t0 = 0; t0 < count; t0 += TILE) {
        int tn = min(TILE, count - t0);
        __syncthreads();
        for (int j = threadIdx.x; j < tn; j += 256) tile[j] = pre[t0 + j];
        __syncthreads();
        if (has) {
            for (int i = lane; i < tn; i += 32) {
                float4 v = tile[i];
                float dx = v.x - u.x, dy = v.y - u.y, dz = v.z - u.z;
                float q = fmaf(dx, dx, fmaf(dy, dy, dz * dz));
                if (q <= qthr) {
                    float d = TWO_R * asinf(0.5f * sqrtf(q));
                    s += __expf((dmin - d) * INV_TAU);   // min elem -> exp(0)=1
                }
            }
        }
    }
    #pragma unroll
    for (int off = 16; off > 0; off >>= 1)
        s += __shfl_xor_sync(0xFFFFFFFFu, s, off);

    if (has && lane == 0) {
        bool valid = (count > 0);
        g_softmin[row] = valid ? (dmin - TAU * logf(s)) : 0.0f;
        g_validf[row]  = valid ? 1.0f : 0.0f;
    }
}

// ---------------------------------------------------------------------------
// Kernel 4: deterministic final reduction (1024 threads, fixed order)
// ---------------------------------------------------------------------------
__global__ void __launch_bounds__(1024) reduce_kernel(float* __restrict__ out) {
    __shared__ float ss[32], sv[32];
    int tid = threadIdx.x;
    float s = 0.0f, v = 0.0f;
    for (int i = tid; i < B_ROWS; i += 1024) {
        s += g_softmin[i];
        v += g_validf[i];
    }
    #pragma unroll
    for (int off = 16; off > 0; off >>= 1) {
        s += __shfl_xor_sync(0xFFFFFFFFu, s, off);
        v += __shfl_xor_sync(0xFFFFFFFFu, v, off);
    }
    int warp = tid >> 5, lane = tid & 31;
    if (lane == 0) { ss[warp] = s; sv[warp] = v; }
    __syncthreads();
    if (warp == 0) {
        s = ss[lane]; v = sv[lane];
        #pragma unroll
        for (int off = 16; off > 0; off >>= 1) {
            s += __shfl_xor_sync(0xFFFFFFFFu, s, off);
            v += __shfl_xor_sync(0xFFFFFFFFu, v, off);
        }
        if (lane == 0) out[0] = s / fmaxf(v, 1.0f);
    }
}

// ---------------------------------------------------------------------------
// Launch — inputs identified by element count (immune to ordering):
//   preds_lonlat : 16384   bin_coords : 1024000
//   x_vals       : 24576/49152   bin_counts : 125/250
// ---------------------------------------------------------------------------
extern "C" void kernel_launch(void* const* d_in, const int* in_sizes, int n_in,
                              void* d_out, int out_size) {
    const float* preds      = nullptr;
    const float* bin_coords = nullptr;
    const void*  x_vals     = nullptr;
    const void*  bin_counts = nullptr;

    for (int i = 0; i < n_in; i++) {
        switch (in_sizes[i]) {
            case 16384:   preds      = (const float*)d_in[i]; break;
            case 1024000: bin_coords = (const float*)d_in[i]; break;
            case 24576:
            case 49152:   x_vals     = d_in[i]; break;
            case 125:
            case 250:     bin_counts = d_in[i]; break;
            default: break;
        }
    }

    detect_kernel<<<1, 256>>>(x_vals);

    const int NPRE = NBINS * M_CAND;
    precompute_kernel<<<(NPRE + 255) / 256, 256>>>(bin_coords);

    binning_kernel<<<(B_ROWS + 255) / 256, 256>>>(preds, x_vals);

    main_kernel<<<dim3(NBINS, ROWCAP / 8), 256>>>(bin_counts);

    reduce_kernel<<<1, 1024>>>((float*)d_out);
}